// round 5
// baseline (speedup 1.0000x reference)
#include <cuda_runtime.h>

// FasterTensorProduct, factored form:
//   out[b,n1,n2,o] = sum_{s=0..3} sh[b,n1,s] * P[b,n2,s,o]
// where P[b,n2,s,:] = y(x_{b,n2}, e_s) is the bilinear map evaluated on the
// four sh basis vectors.
//
// Kernel A computes P (4*128*272 float4 = 2.23 MB, L2-resident device global).
// Kernel B is a pure write-bandwidth fan-out.
//
// Dims: M0E=64, M1O=32, M1E=32, M0O=16, IN_DIM=OUT_DIM=272, B=4, N=128.
// Weights (flat, row-major, each block scaled by 1/sqrt(rows)):
//   W0e at 0     : (96,64)
//   W1o at 6144  : (128,32)
//   W1e at 10240 : (80,32)
//   W0o at 12800 : (48,16)

#define B_DIM 4
#define N_DIM 128
#define IO_DIM 272

__device__ float4 g_Pbuf[B_DIM * N_DIM * IO_DIM];   // [b][n2][o] -> (P_s0..P_s3)

// ---------------------------------------------------------------------------
// Kernel A: compute P
// ---------------------------------------------------------------------------
__global__ __launch_bounds__(272) void ftp_precompute(
    const float* __restrict__ in_, const float* __restrict__ w)
{
    __shared__ float xs[IO_DIM];

    const int tid = threadIdx.x;
    const int n2  = blockIdx.x;
    const int b   = blockIdx.y;

    const float* xrow = in_ + (size_t)(b * N_DIM + n2) * IO_DIM;
    xs[tid] = xrow[tid];
    __syncthreads();

    const float inv2 = 0.7071067811865476f;   // 1/sqrt(2)
    const float inv3 = 0.5773502691896258f;   // 1/sqrt(3)

    float p0, p1, p2, p3;
    const int o = tid;

    if (o < 64) {
        // y0e: out0e = [x0e*sh0, (x1o . sh1)/sqrt3], W0e (96,64), 1/sqrt(96)
        const float s = 0.10206207261596575f;
        float a0 = 0.f;
        #pragma unroll
        for (int k = 0; k < 64; k++) a0 += xs[k] * w[k * 64 + o];
        float a1 = 0.f, a2 = 0.f, a3 = 0.f;
        #pragma unroll
        for (int m = 0; m < 32; m++) {
            float wv = w[(64 + m) * 64 + o];
            a1 += xs[64 + 3 * m + 0] * wv;
            a2 += xs[64 + 3 * m + 1] * wv;
            a3 += xs[64 + 3 * m + 2] * wv;
        }
        p0 = a0 * s;
        p1 = a1 * (s * inv3);
        p2 = a2 * (s * inv3);
        p3 = a3 * (s * inv3);
    } else if (o < 160) {
        // y1o: o = 64 + oo*3 + cp. W1o (128,32) at 6144, 1/sqrt(128)
        // rows: [0:64) x0e*sh1[c], [64:96) x1o*sh0, [96:128) cross(x1e,sh1)/sqrt2
        const float s  = 0.08838834764831845f;
        const int  t  = o - 64;
        const int  oo = t / 3;
        const int  cp = t - 3 * oo;
        const int  ca = (cp + 1) % 3;
        const int  cb = (cp + 2) % 3;
        const float* w1 = w + 6144;
        float A = 0.f, Bacc = 0.f, Ca = 0.f, Cb = 0.f;
        #pragma unroll
        for (int k = 0; k < 64; k++) Bacc += xs[k] * w1[k * 32 + oo];
        #pragma unroll
        for (int m = 0; m < 32; m++) {
            A += xs[64 + 3 * m + cp] * w1[(64 + m) * 32 + oo];
            float wv = w1[(96 + m) * 32 + oo];
            Ca += xs[160 + 3 * m + cb] * wv;
            Cb += xs[160 + 3 * m + ca] * wv;
        }
        p0 = A * s;
        float vB = Bacc * s;
        float vA = -Ca * (s * inv2);
        float vC =  Cb * (s * inv2);
        p1 = (cp == 0) ? vB : ((ca == 0) ? vA : vC);
        p2 = (cp == 1) ? vB : ((ca == 1) ? vA : vC);
        p3 = (cp == 2) ? vB : ((ca == 2) ? vA : vC);
    } else if (o < 256) {
        // y1e: o = 160 + oo*3 + cp. W1e (80,32) at 10240, 1/sqrt(80)
        // rows: [0:32) cross(x1o,sh1)/sqrt2, [32:64) x1e*sh0, [64:80) x0o*sh1[c]
        const float s  = 0.11180339887498949f;
        const int  t  = o - 160;
        const int  oo = t / 3;
        const int  cp = t - 3 * oo;
        const int  ca = (cp + 1) % 3;
        const int  cb = (cp + 2) % 3;
        const float* w2 = w + 10240;
        float A = 0.f, Bacc = 0.f, Ca = 0.f, Cb = 0.f;
        #pragma unroll
        for (int m = 0; m < 32; m++) {
            A += xs[160 + 3 * m + cp] * w2[(32 + m) * 32 + oo];
            float wv = w2[m * 32 + oo];
            Ca += xs[64 + 3 * m + cb] * wv;
            Cb += xs[64 + 3 * m + ca] * wv;
        }
        #pragma unroll
        for (int k = 0; k < 16; k++) Bacc += xs[256 + k] * w2[(64 + k) * 32 + oo];
        p0 = A * s;
        float vB = Bacc * s;
        float vA = -Ca * (s * inv2);
        float vC =  Cb * (s * inv2);
        p1 = (cp == 0) ? vB : ((ca == 0) ? vA : vC);
        p2 = (cp == 1) ? vB : ((ca == 1) ? vA : vC);
        p3 = (cp == 2) ? vB : ((ca == 2) ? vA : vC);
    } else {
        // y0o: o = 256 + oy. W0o (48,16) at 12800, 1/sqrt(48)
        const float s  = 0.14433756729740645f;
        const int  oy = o - 256;
        const float* w3 = w + 12800;
        float a0 = 0.f;
        #pragma unroll
        for (int k = 0; k < 16; k++) a0 += xs[256 + k] * w3[(32 + k) * 16 + oy];
        float a1 = 0.f, a2 = 0.f, a3 = 0.f;
        #pragma unroll
        for (int m = 0; m < 32; m++) {
            float wv = w3[m * 16 + oy];
            a1 += xs[160 + 3 * m + 0] * wv;
            a2 += xs[160 + 3 * m + 1] * wv;
            a3 += xs[160 + 3 * m + 2] * wv;
        }
        p0 = a0 * s;
        p1 = a1 * (s * inv3);
        p2 = a2 * (s * inv3);
        p3 = a3 * (s * inv3);
    }

    g_Pbuf[(b * N_DIM + n2) * IO_DIM + o] = make_float4(p0, p1, p2, p3);
}

// ---------------------------------------------------------------------------
// Kernel B: fan-out   out[b,n1,n2,:] = sh[b,n1,:] . P[b,n2,:,:]
// grid = (n2=128, b=4, half=2); block = 272 threads
// thread: o4 = tid%68 (float4 column), g = tid/68; n1 = half*64 + g + 4*i
// ---------------------------------------------------------------------------
__global__ __launch_bounds__(272) void ftp_fanout(
    const float4* __restrict__ sh4, float4* __restrict__ outv)
{
    __shared__ float4 shs[64];

    const int tid  = threadIdx.x;
    const int n2   = blockIdx.x;
    const int b    = blockIdx.y;
    const int half = blockIdx.z;

    if (tid < 64)
        shs[tid] = sh4[b * N_DIM + half * 64 + tid];
    __syncthreads();

    const int o4 = tid % 68;
    const int g  = tid / 68;

    const float4* __restrict__ Prow = g_Pbuf + (b * N_DIM + n2) * IO_DIM + o4 * 4;
    const float4 q0 = Prow[0];
    const float4 q1 = Prow[1];
    const float4 q2 = Prow[2];
    const float4 q3 = Prow[3];

    // output float4 index: ((b*128 + n1)*128 + n2)*68 + o4, n1 = half*64 + g + 4*i
    size_t base = ((size_t)(b * N_DIM + half * 64 + g) * N_DIM + n2) * 68 + o4;
    const size_t stride = (size_t)4 * N_DIM * 68;

    #pragma unroll
    for (int i = 0; i < 16; i++) {
        float4 s4 = shs[g + 4 * i];
        float4 r;
        r.x = q0.x * s4.x + q0.y * s4.y + q0.z * s4.z + q0.w * s4.w;
        r.y = q1.x * s4.x + q1.y * s4.y + q1.z * s4.z + q1.w * s4.w;
        r.z = q2.x * s4.x + q2.y * s4.y + q2.z * s4.z + q2.w * s4.w;
        r.w = q3.x * s4.x + q3.y * s4.y + q3.z * s4.z + q3.w * s4.w;
        outv[base + (size_t)i * stride] = r;
    }
}

extern "C" void kernel_launch(void* const* d_in, const int* in_sizes, int n_in,
                              void* d_out, int out_size) {
    const float* in_ = nullptr;
    const float* sh  = nullptr;
    const float* w   = nullptr;
    for (int i = 0; i < n_in; i++) {
        if (in_sizes[i] == B_DIM * N_DIM * IO_DIM)      in_ = (const float*)d_in[i];
        else if (in_sizes[i] == B_DIM * N_DIM * 4)      sh  = (const float*)d_in[i];
        else if (in_sizes[i] == 13568)                  w   = (const float*)d_in[i];
    }
    if (!in_) in_ = (const float*)d_in[0];
    if (!sh)  sh  = (const float*)d_in[1];
    if (!w)   w   = (const float*)d_in[2];

    float4* outv = (float4*)d_out;

    dim3 gridA(N_DIM, B_DIM);
    ftp_precompute<<<gridA, 272>>>(in_, w);

    dim3 gridB(N_DIM, B_DIM, 2);
    ftp_fanout<<<gridB, 272>>>((const float4*)sh, outv);
}